// round 2
// baseline (speedup 1.0000x reference)
#include <cuda_runtime.h>
#include <math.h>

#define NB 64
#define NT_TIME 512
#define NI 256
#define NH 1024
#define NOISEF 0.1f

#define KSPLIT 16
#define NTILE 16

// Scratch (static device globals: no allocation at runtime)
__device__ float g_h[2][NB * NH];            // double-buffered hidden state
__device__ float g_part[KSPLIT][NB * NH];    // split-K partial slabs
__device__ float g_alpha[NH];                // per-unit alpha
__device__ int   g_cnt[NTILE];               // per-column-tile arrival counters

__global__ void init_kernel(const float* __restrict__ taus) {
    int idx = blockIdx.x * blockDim.x + threadIdx.x;
    if (idx < NB * NH) g_h[0][idx] = 0.0f;
    if (idx < NH) {
        float s = 1.0f / (1.0f + expf(-taus[idx]));
        float tau = s * 90.0f + 10.0f;
        g_alpha[idx] = 10.0f / tau;
    }
    if (idx < NTILE) g_cnt[idx] = 0;
}

// ---------------------------------------------------------------------------
// Input projection: out[r][j] = sum_i x[r][i]*w[j][i] + bias[j] + NOISE*eps[r][j]
// r = b*T + t flattened (32768 rows). 64x64 tile per block, 4x4 per thread.
// ---------------------------------------------------------------------------
__global__ void __launch_bounds__(256) proj_kernel(
    const float* __restrict__ x, const float* __restrict__ w,
    const float* __restrict__ bias, const float* __restrict__ eps,
    float* __restrict__ out)
{
    __shared__ float xs[16][68];
    __shared__ float ws[16][68];
    const int tid = threadIdx.x;
    const int jj = tid & 15;       // 0..15 (col group)
    const int bb = tid >> 4;       // 0..15 (row group)
    const int j0 = blockIdx.x * 64;
    const int r0 = blockIdx.y * 64;
    const int lr = tid >> 2;            // 0..63 loader row
    const int lk = (tid & 3) << 2;      // 0,4,8,12 loader k

    float acc[4][4];
#pragma unroll
    for (int i = 0; i < 4; i++)
#pragma unroll
        for (int c = 0; c < 4; c++) acc[i][c] = 0.0f;

    for (int k0 = 0; k0 < NI; k0 += 16) {
        float4 xv = *(const float4*)(x + (r0 + lr) * NI + k0 + lk);
        float4 wv = *(const float4*)(w + (j0 + lr) * NI + k0 + lk);
        xs[lk + 0][lr] = xv.x; xs[lk + 1][lr] = xv.y;
        xs[lk + 2][lr] = xv.z; xs[lk + 3][lr] = xv.w;
        ws[lk + 0][lr] = wv.x; ws[lk + 1][lr] = wv.y;
        ws[lk + 2][lr] = wv.z; ws[lk + 3][lr] = wv.w;
        __syncthreads();
#pragma unroll
        for (int k = 0; k < 16; k++) {
            float4 a  = *(const float4*)&xs[k][bb << 2];
            float4 c4 = *(const float4*)&ws[k][jj << 2];
            acc[0][0] = fmaf(a.x, c4.x, acc[0][0]);
            acc[0][1] = fmaf(a.x, c4.y, acc[0][1]);
            acc[0][2] = fmaf(a.x, c4.z, acc[0][2]);
            acc[0][3] = fmaf(a.x, c4.w, acc[0][3]);
            acc[1][0] = fmaf(a.y, c4.x, acc[1][0]);
            acc[1][1] = fmaf(a.y, c4.y, acc[1][1]);
            acc[1][2] = fmaf(a.y, c4.z, acc[1][2]);
            acc[1][3] = fmaf(a.y, c4.w, acc[1][3]);
            acc[2][0] = fmaf(a.z, c4.x, acc[2][0]);
            acc[2][1] = fmaf(a.z, c4.y, acc[2][1]);
            acc[2][2] = fmaf(a.z, c4.z, acc[2][2]);
            acc[2][3] = fmaf(a.z, c4.w, acc[2][3]);
            acc[3][0] = fmaf(a.w, c4.x, acc[3][0]);
            acc[3][1] = fmaf(a.w, c4.y, acc[3][1]);
            acc[3][2] = fmaf(a.w, c4.z, acc[3][2]);
            acc[3][3] = fmaf(a.w, c4.w, acc[3][3]);
        }
        __syncthreads();
    }

    float4 bi = *(const float4*)(bias + j0 + (jj << 2));
#pragma unroll
    for (int i = 0; i < 4; i++) {
        int r = r0 + (bb << 2) + i;
        long off = (long)r * NH + j0 + (jj << 2);
        float4 ev = *(const float4*)(eps + off);
        float4 o;
        o.x = acc[i][0] + bi.x + NOISEF * ev.x;
        o.y = acc[i][1] + bi.y + NOISEF * ev.y;
        o.z = acc[i][2] + bi.z + NOISEF * ev.z;
        o.w = acc[i][3] + bi.w + NOISEF * ev.w;
        *(float4*)(out + off) = o;
    }
}

// ---------------------------------------------------------------------------
// One recurrence step. Grid (NTILE, KSPLIT). Block (nt, ks) computes the
// partial GEMM h_in[64 x 64k-slice] * W[slice x 64 cols] into g_part[ks].
// Last-arriving block per column tile sums slabs (fixed order, deterministic)
// and applies the leaky-tanh update, writing out[b][t][:] and h_out.
// ---------------------------------------------------------------------------
__global__ void __launch_bounds__(256) step_kernel(
    const float* __restrict__ W, float* __restrict__ out, int t, int par)
{
    __shared__ float hs[16][68];
    __shared__ float ws[16][68];
    __shared__ int s_last;
    const float* __restrict__ h_in = g_h[par];
    float* __restrict__ h_out = g_h[par ^ 1];

    const int tid = threadIdx.x;
    const int jj = tid & 15;
    const int bb = tid >> 4;
    const int nt = blockIdx.x;
    const int ks = blockIdx.y;
    const int j0 = nt * 64;
    const int lb = tid >> 2;            // 0..63 (h-loader batch)
    const int lk = (tid & 3) << 2;      // 0,4,8,12
    const int wk = tid >> 4;            // 0..15 (W-loader k)
    const int wj = (tid & 15) << 2;     // 0..60 (W-loader j)

    float acc[4][4];
#pragma unroll
    for (int i = 0; i < 4; i++)
#pragma unroll
        for (int c = 0; c < 4; c++) acc[i][c] = 0.0f;

    for (int kc = 0; kc < 64; kc += 16) {
        int k0 = ks * 64 + kc;
        float4 hv = *(const float4*)(h_in + lb * NH + k0 + lk);
        float4 wv = *(const float4*)(W + (k0 + wk) * NH + j0 + wj);
        hs[lk + 0][lb] = hv.x; hs[lk + 1][lb] = hv.y;
        hs[lk + 2][lb] = hv.z; hs[lk + 3][lb] = hv.w;
        *(float4*)&ws[wk][wj] = wv;
        __syncthreads();
#pragma unroll
        for (int k = 0; k < 16; k++) {
            float4 a  = *(const float4*)&hs[k][bb << 2];
            float4 c4 = *(const float4*)&ws[k][jj << 2];
            acc[0][0] = fmaf(a.x, c4.x, acc[0][0]);
            acc[0][1] = fmaf(a.x, c4.y, acc[0][1]);
            acc[0][2] = fmaf(a.x, c4.z, acc[0][2]);
            acc[0][3] = fmaf(a.x, c4.w, acc[0][3]);
            acc[1][0] = fmaf(a.y, c4.x, acc[1][0]);
            acc[1][1] = fmaf(a.y, c4.y, acc[1][1]);
            acc[1][2] = fmaf(a.y, c4.z, acc[1][2]);
            acc[1][3] = fmaf(a.y, c4.w, acc[1][3]);
            acc[2][0] = fmaf(a.z, c4.x, acc[2][0]);
            acc[2][1] = fmaf(a.z, c4.y, acc[2][1]);
            acc[2][2] = fmaf(a.z, c4.z, acc[2][2]);
            acc[2][3] = fmaf(a.z, c4.w, acc[2][3]);
            acc[3][0] = fmaf(a.w, c4.x, acc[3][0]);
            acc[3][1] = fmaf(a.w, c4.y, acc[3][1]);
            acc[3][2] = fmaf(a.w, c4.z, acc[3][2]);
            acc[3][3] = fmaf(a.w, c4.w, acc[3][3]);
        }
        __syncthreads();
    }

    // Store partial slab (unique (ks, b, j) region -> plain stores, no atomics)
    float* p = g_part[ks];
#pragma unroll
    for (int i = 0; i < 4; i++) {
        int b = (bb << 2) + i;
        *(float4*)(p + b * NH + j0 + (jj << 2)) =
            make_float4(acc[i][0], acc[i][1], acc[i][2], acc[i][3]);
    }

    __threadfence();
    __syncthreads();
    if (tid == 0) {
        int old = atomicAdd(&g_cnt[nt], 1);
        s_last = (old == KSPLIT - 1) ? 1 : 0;
    }
    __syncthreads();
    if (!s_last) return;
    __threadfence();  // acquire: make all slabs visible

    const float4 al = *(const float4*)(g_alpha + j0 + (jj << 2));
#pragma unroll
    for (int i = 0; i < 4; i++) {
        int b = (bb << 2) + i;
        int hoff = b * NH + j0 + (jj << 2);
        float4 s = make_float4(0.f, 0.f, 0.f, 0.f);
#pragma unroll
        for (int q = 0; q < KSPLIT; q++) {
            float4 pv = *(const float4*)(g_part[q] + hoff);
            s.x += pv.x; s.y += pv.y; s.z += pv.z; s.w += pv.w;
        }
        long ooff = ((long)b * NT_TIME + t) * NH + j0 + (jj << 2);
        float4 pre = *(const float4*)(out + ooff);
        float4 hv  = *(const float4*)(h_in + hoff);
        float4 hn;
        hn.x = (1.0f - al.x) * hv.x + al.x * tanhf(pre.x + s.x);
        hn.y = (1.0f - al.y) * hv.y + al.y * tanhf(pre.y + s.y);
        hn.z = (1.0f - al.z) * hv.z + al.z * tanhf(pre.z + s.z);
        hn.w = (1.0f - al.w) * hv.w + al.w * tanhf(pre.w + s.w);
        *(float4*)(out + ooff) = hn;
        *(float4*)(h_out + hoff) = hn;
    }
    if (tid == 0) g_cnt[nt] = 0;   // reset for next step (kernel boundary = fence)
}

extern "C" void kernel_launch(void* const* d_in, const int* in_sizes, int n_in,
                              void* d_out, int out_size) {
    const float* x    = (const float*)d_in[0];  // [B,T,I]
    const float* eps  = (const float*)d_in[1];  // [B,T,H]
    const float* in_w = (const float*)d_in[2];  // [H,I]
    const float* in_b = (const float*)d_in[3];  // [H]
    const float* W    = (const float*)d_in[4];  // [H,H]
    const float* taus = (const float*)d_in[5];  // [H]
    float* out = (float*)d_out;                 // [B,T,H]

    init_kernel<<<(NB * NH + 255) / 256, 256>>>(taus);

    dim3 pgrid(NH / 64, (NB * NT_TIME) / 64);   // (16, 512)
    proj_kernel<<<pgrid, 256>>>(x, in_w, in_b, eps, out);

    for (int t = 0; t < NT_TIME; t++) {
        step_kernel<<<dim3(NTILE, KSPLIT), 256>>>(W, out, t, t & 1);
    }
}

// round 3
// speedup vs baseline: 1.1511x; 1.1511x over previous
#include <cuda_runtime.h>
#include <math.h>

#define NB 64
#define TT 512
#define NI 256
#define NH 1024
#define NOISEF 0.1f
#define NTILE 16          // N tiles of 64 columns
#define KS 8              // K slices of 128
#define NBLK (NTILE * KS) // 128 persistent blocks

// ---- static device scratch (no runtime allocation) ----
__device__ float g_h[2][NB * NH];         // double-buffered hidden state
__device__ float g_part[KS][NB * NH];     // split-K partial slabs
__device__ float g_alpha[NH];
__device__ float g_wt[NI * NH];           // transposed in_w: [I][H]
__device__ int   g_cnt[NTILE];            // split-K arrival counters
__device__ int   g_flag[NTILE];           // epilogue-done step counters
__device__ int   g_rd[NTILE];             // reader (staging) arrival counters

// ---- f32x2 packed-FMA helpers (Blackwell FFMA2, PTX-only) ----
__device__ __forceinline__ unsigned long long pk2(float a, float b) {
    unsigned long long r;
    asm("mov.b64 %0, {%1, %2};" : "=l"(r) : "r"(__float_as_uint(a)), "r"(__float_as_uint(b)));
    return r;
}
__device__ __forceinline__ float2 upk2(unsigned long long v) {
    unsigned int lo, hi;
    asm("mov.b64 {%0, %1}, %2;" : "=r"(lo), "=r"(hi) : "l"(v));
    return make_float2(__uint_as_float(lo), __uint_as_float(hi));
}
__device__ __forceinline__ unsigned long long ffma2(unsigned long long a,
                                                    unsigned long long b,
                                                    unsigned long long c) {
    unsigned long long d;
    asm("fma.rn.f32x2 %0, %1, %2, %3;" : "=l"(d) : "l"(a), "l"(b), "l"(c));
    return d;
}

__global__ void init_kernel(const float* __restrict__ taus) {
    int idx = blockIdx.x * blockDim.x + threadIdx.x;
    if (idx < NB * NH) g_h[0][idx] = 0.0f;
    if (idx < NH) {
        float s = 1.0f / (1.0f + expf(-taus[idx]));
        g_alpha[idx] = 10.0f / (s * 90.0f + 10.0f);
    }
    if (idx < NTILE) { g_cnt[idx] = 0; g_flag[idx] = 0; g_rd[idx] = 0; }
}

// transpose in_w [H][I] -> g_wt [I][H]
__global__ void transpose_kernel(const float* __restrict__ w) {
    __shared__ float t[32][33];
    int bi = blockIdx.x * 32;   // I dim
    int bh = blockIdx.y * 32;   // H dim
    int tx = threadIdx.x, ty = threadIdx.y;
    for (int i = ty; i < 32; i += 8) t[i][tx] = w[(bh + i) * NI + bi + tx];
    __syncthreads();
    for (int i = ty; i < 32; i += 8) g_wt[(bi + i) * NH + bh + tx] = t[tx][i];
}

// ---------------------------------------------------------------------------
// Input projection: out[r][j] = x[r]·in_w[j] + bias[j] + NOISE*eps[r][j]
// 64x64 tile / block, 4x4 per thread, FFMA2 inner loop.
// ---------------------------------------------------------------------------
__global__ void __launch_bounds__(256) proj_kernel(
    const float* __restrict__ x, const float* __restrict__ bias,
    const float* __restrict__ eps, float* __restrict__ out)
{
    __shared__ float xs[64][20];   // xs[r][k]
    __shared__ float ws[16][68];   // ws[k][j]
    const int tid = threadIdx.x;
    const int rg = tid >> 4, cg = tid & 15;
    const int r4 = rg << 2, c4 = cg << 2;
    const int j0 = blockIdx.x * 64;
    const int r0 = blockIdx.y * 64;
    const int lr = tid >> 2, lk = (tid & 3) << 2;       // x loader
    const int wk = tid >> 4, wj = (tid & 15) << 2;      // w loader

    unsigned long long acc[4][2];
#pragma unroll
    for (int i = 0; i < 4; i++) { acc[i][0] = 0ull; acc[i][1] = 0ull; }

    for (int k0 = 0; k0 < NI; k0 += 16) {
        *(float4*)&xs[lr][lk] = *(const float4*)(x + (r0 + lr) * NI + k0 + lk);
        *(float4*)&ws[wk][wj] = *(const float4*)(g_wt + (k0 + wk) * NH + j0 + wj);
        __syncthreads();
#pragma unroll
        for (int k = 0; k < 16; k += 4) {
            ulonglong2 b0 = *(const ulonglong2*)&ws[k + 0][c4];
            ulonglong2 b1 = *(const ulonglong2*)&ws[k + 1][c4];
            ulonglong2 b2 = *(const ulonglong2*)&ws[k + 2][c4];
            ulonglong2 b3 = *(const ulonglong2*)&ws[k + 3][c4];
#pragma unroll
            for (int i = 0; i < 4; i++) {
                float4 a = *(const float4*)&xs[r4 + i][k];
                unsigned long long p;
                p = pk2(a.x, a.x); acc[i][0] = ffma2(p, b0.x, acc[i][0]); acc[i][1] = ffma2(p, b0.y, acc[i][1]);
                p = pk2(a.y, a.y); acc[i][0] = ffma2(p, b1.x, acc[i][0]); acc[i][1] = ffma2(p, b1.y, acc[i][1]);
                p = pk2(a.z, a.z); acc[i][0] = ffma2(p, b2.x, acc[i][0]); acc[i][1] = ffma2(p, b2.y, acc[i][1]);
                p = pk2(a.w, a.w); acc[i][0] = ffma2(p, b3.x, acc[i][0]); acc[i][1] = ffma2(p, b3.y, acc[i][1]);
            }
        }
        __syncthreads();
    }

    float4 bi = *(const float4*)(bias + j0 + c4);
#pragma unroll
    for (int i = 0; i < 4; i++) {
        int r = r0 + r4 + i;
        int off = r * NH + j0 + c4;
        float4 ev = *(const float4*)(eps + off);
        float2 lo = upk2(acc[i][0]);
        float2 hi = upk2(acc[i][1]);
        float4 o;
        o.x = lo.x + bi.x + NOISEF * ev.x;
        o.y = lo.y + bi.y + NOISEF * ev.y;
        o.z = hi.x + bi.z + NOISEF * ev.z;
        o.w = hi.y + bi.w + NOISEF * ev.w;
        *(float4*)(out + off) = o;
    }
}

// ---------------------------------------------------------------------------
// Persistent scan kernel: 128 blocks, each owns a (nt, ks) tile of W in smem
// and loops over all 512 time steps with flag-based point-to-point sync.
// ---------------------------------------------------------------------------
__global__ void __launch_bounds__(256) scan_kernel(
    const float* __restrict__ W, float* __restrict__ out)
{
    extern __shared__ float smem[];
    float* ws_s = smem;                 // [128][64] W tile (K-slice x N-tile)
    float* hs_s = smem + 128 * 64;      // [64][132] h slice (batch x K-slice)
#define HS(b, k) hs_s[(b) * 132 + (k)]
    __shared__ int s_last;

    const int tid = threadIdx.x;
    const int nt = blockIdx.x & 15;
    const int ks = blockIdx.x >> 4;
    const int j0 = nt * 64;
    const int k0 = ks * 128;
    const int rg = tid >> 4, cg = tid & 15;
    const int r4 = rg << 2, c4 = cg << 2;

    // Load W tile once: ws_s[k][j] = W[k0+k][j0+j]
    for (int idx = tid; idx < 128 * 16; idx += 256) {
        int k = idx >> 4, j = (idx & 15) << 2;
        *(float4*)&ws_s[k * 64 + j] = *(const float4*)(W + (k0 + k) * NH + j0 + j);
    }
    __syncthreads();

    volatile int* vflag = (volatile int*)g_flag;
    volatile int* vrd   = (volatile int*)g_rd;

    for (int t = 0; t < TT; t++) {
        // wait: h producers (tiles 2ks, 2ks+1) and slab consumer (tile nt) at step t
        if (tid < 3) {
            int tgt = (tid == 0) ? (2 * ks) : (tid == 1) ? (2 * ks + 1) : nt;
            while (vflag[tgt] < t) __nanosleep(32);
        }
        __syncthreads();

        // stage h slice: hs_s[b][k] = h_in[b][k0+k]  (L2-coherent reads)
        const float* hin = g_h[t & 1];
        for (int idx = tid; idx < 2048; idx += 256) {
            int b = idx >> 5, kk = (idx & 31) << 2;
            float4 v = __ldcg((const float4*)(hin + b * NH + k0 + kk));
            *(float4*)&HS(b, kk) = v;
        }
        __syncthreads();
        if (tid == 0) atomicAdd(&g_rd[2 * ks], 1);
        if (tid == 1) atomicAdd(&g_rd[2 * ks + 1], 1);

        // partial GEMM: acc[4 rows][2 col-pairs] over K=128, FFMA2
        unsigned long long acc[4][2];
#pragma unroll
        for (int i = 0; i < 4; i++) { acc[i][0] = 0ull; acc[i][1] = 0ull; }
#pragma unroll 4
        for (int k = 0; k < 128; k += 4) {
            ulonglong2 b0 = *(const ulonglong2*)&ws_s[(k + 0) * 64 + c4];
            ulonglong2 b1 = *(const ulonglong2*)&ws_s[(k + 1) * 64 + c4];
            ulonglong2 b2 = *(const ulonglong2*)&ws_s[(k + 2) * 64 + c4];
            ulonglong2 b3 = *(const ulonglong2*)&ws_s[(k + 3) * 64 + c4];
#pragma unroll
            for (int i = 0; i < 4; i++) {
                float4 a = *(const float4*)&HS(r4 + i, k);
                unsigned long long p;
                p = pk2(a.x, a.x); acc[i][0] = ffma2(p, b0.x, acc[i][0]); acc[i][1] = ffma2(p, b0.y, acc[i][1]);
                p = pk2(a.y, a.y); acc[i][0] = ffma2(p, b1.x, acc[i][0]); acc[i][1] = ffma2(p, b1.y, acc[i][1]);
                p = pk2(a.z, a.z); acc[i][0] = ffma2(p, b2.x, acc[i][0]); acc[i][1] = ffma2(p, b2.y, acc[i][1]);
                p = pk2(a.w, a.w); acc[i][0] = ffma2(p, b3.x, acc[i][0]); acc[i][1] = ffma2(p, b3.y, acc[i][1]);
            }
        }

        // store partial slab (unique region per (ks,nt): plain stores)
        float* part = g_part[ks];
#pragma unroll
        for (int i = 0; i < 4; i++) {
            float2 lo = upk2(acc[i][0]);
            float2 hi = upk2(acc[i][1]);
            *(float4*)(part + (r4 + i) * NH + j0 + c4) = make_float4(lo.x, lo.y, hi.x, hi.y);
        }

        __threadfence();
        __syncthreads();
        if (tid == 0) {
            int old = atomicAdd(&g_cnt[nt], 1);
            s_last = (old == KS - 1) ? 1 : 0;
        }
        __syncthreads();

        if (s_last) {
            __threadfence();   // acquire: other blocks' slabs
            // sum slabs (deterministic fixed order), L2-coherent reads
            float4 s[4];
#pragma unroll
            for (int i = 0; i < 4; i++)
                s[i] = __ldcg((const float4*)(g_part[0] + (r4 + i) * NH + j0 + c4));
#pragma unroll
            for (int q = 1; q < KS; q++)
#pragma unroll
                for (int i = 0; i < 4; i++) {
                    float4 v = __ldcg((const float4*)(g_part[q] + (r4 + i) * NH + j0 + c4));
                    s[i].x += v.x; s[i].y += v.y; s[i].z += v.z; s[i].w += v.w;
                }

            // WAR guard: readers of buffer (t+1)&1 (= step t-1 stagers) must be done
            if (tid == 0) { while (vrd[nt] < 16 * t) __nanosleep(32); }
            __syncthreads();

            const float* hin2 = g_h[t & 1];
            float* hout = g_h[(t + 1) & 1];
            float4 al = *(const float4*)(g_alpha + j0 + c4);
#pragma unroll
            for (int i = 0; i < 4; i++) {
                int b = r4 + i;
                int hoff = b * NH + j0 + c4;
                int ooff = (b * TT + t) * NH + j0 + c4;
                float4 pre = *(const float4*)(out + ooff);
                float4 hv = __ldcg((const float4*)(hin2 + hoff));
                float4 hn;
                hn.x = (1.0f - al.x) * hv.x + al.x * tanhf(pre.x + s[i].x);
                hn.y = (1.0f - al.y) * hv.y + al.y * tanhf(pre.y + s[i].y);
                hn.z = (1.0f - al.z) * hv.z + al.z * tanhf(pre.z + s[i].z);
                hn.w = (1.0f - al.w) * hv.w + al.w * tanhf(pre.w + s[i].w);
                *(float4*)(out + ooff) = hn;
                *(float4*)(hout + hoff) = hn;
            }
            __threadfence();
            __syncthreads();
            if (tid == 0) {
                atomicExch(&g_cnt[nt], 0);
                __threadfence();
                atomicExch(&g_flag[nt], t + 1);   // release: step t done for tile nt
            }
        }
    }
#undef HS
}

extern "C" void kernel_launch(void* const* d_in, const int* in_sizes, int n_in,
                              void* d_out, int out_size) {
    const float* x    = (const float*)d_in[0];  // [B,T,I]
    const float* eps  = (const float*)d_in[1];  // [B,T,H]
    const float* in_w = (const float*)d_in[2];  // [H,I]
    const float* in_b = (const float*)d_in[3];  // [H]
    const float* W    = (const float*)d_in[4];  // [H,H]
    const float* taus = (const float*)d_in[5];  // [H]
    float* out = (float*)d_out;                 // [B,T,H]

    static int attr_done = 0;
    const int scan_smem = (128 * 64 + 64 * 132) * sizeof(float);  // ~66.6 KB
    if (!attr_done) {
        cudaFuncSetAttribute(scan_kernel, cudaFuncAttributeMaxDynamicSharedMemorySize, scan_smem);
        attr_done = 1;
    }

    init_kernel<<<(NB * NH + 255) / 256, 256>>>(taus);
    transpose_kernel<<<dim3(NI / 32, NH / 32), dim3(32, 8)>>>(in_w);

    dim3 pgrid(NH / 64, (NB * TT) / 64);   // (16, 512)
    proj_kernel<<<pgrid, 256>>>(x, in_b, eps, out);

    scan_kernel<<<NBLK, 256, scan_smem>>>(W, out);
}

// round 4
// speedup vs baseline: 1.7667x; 1.5348x over previous
#include <cuda_runtime.h>
#include <math.h>

#define NB 64
#define TT 512
#define NI 256
#define NH 1024
#define NOISEF 0.1f
#define NTILE 16          // N tiles of 64 columns
#define KS 8              // K slices of 128
#define NBLK (NTILE * KS) // 128 persistent blocks

// ---- static device scratch (no runtime allocation) ----
__device__ float g_h[2][NB * NH];         // double-buffered hidden state
__device__ float g_part[KS][NB * NH];     // split-K partial slabs (row-major [b][j])
__device__ float g_alpha[NH];
__device__ float g_wt[NI * NH];           // transposed in_w: [I][H]
__device__ int   g_cnt;                   // cumulative slab arrivals (target 128*(t+1))
__device__ int   g_done;                  // cumulative epilogue completions (target 128*(t+1))

// ---- f32x2 packed-FMA helpers (Blackwell FFMA2, PTX-only) ----
__device__ __forceinline__ unsigned long long pk2(float a, float b) {
    unsigned long long r;
    asm("mov.b64 %0, {%1, %2};" : "=l"(r) : "r"(__float_as_uint(a)), "r"(__float_as_uint(b)));
    return r;
}
__device__ __forceinline__ float2 upk2(unsigned long long v) {
    unsigned int lo, hi;
    asm("mov.b64 {%0, %1}, %2;" : "=r"(lo), "=r"(hi) : "l"(v));
    return make_float2(__uint_as_float(lo), __uint_as_float(hi));
}
__device__ __forceinline__ unsigned long long ffma2(unsigned long long a,
                                                    unsigned long long b,
                                                    unsigned long long c) {
    unsigned long long d;
    asm("fma.rn.f32x2 %0, %1, %2, %3;" : "=l"(d) : "l"(a), "l"(b), "l"(c));
    return d;
}

__global__ void init_kernel(const float* __restrict__ taus) {
    int idx = blockIdx.x * blockDim.x + threadIdx.x;
    if (idx < NB * NH) g_h[0][idx] = 0.0f;
    if (idx < NH) {
        float s = 1.0f / (1.0f + expf(-taus[idx]));
        g_alpha[idx] = 10.0f / (s * 90.0f + 10.0f);
    }
    if (idx == 0) { g_cnt = 0; g_done = 0; }
}

// transpose in_w [H][I] -> g_wt [I][H]
__global__ void transpose_kernel(const float* __restrict__ w) {
    __shared__ float t[32][33];
    int bi = blockIdx.x * 32;   // I dim
    int bh = blockIdx.y * 32;   // H dim
    int tx = threadIdx.x, ty = threadIdx.y;
    for (int i = ty; i < 32; i += 8) t[i][tx] = w[(bh + i) * NI + bi + tx];
    __syncthreads();
    for (int i = ty; i < 32; i += 8) g_wt[(bi + i) * NH + bh + tx] = t[tx][i];
}

// ---------------------------------------------------------------------------
// Input projection: out[r][j] = x[r]·in_w[j] + bias[j] + NOISE*eps[r][j]
// ---------------------------------------------------------------------------
__global__ void __launch_bounds__(256) proj_kernel(
    const float* __restrict__ x, const float* __restrict__ bias,
    const float* __restrict__ eps, float* __restrict__ out)
{
    __shared__ float xs[64][20];   // xs[r][k]
    __shared__ float ws[16][68];   // ws[k][j]
    const int tid = threadIdx.x;
    const int rg = tid >> 4, cg = tid & 15;
    const int r4 = rg << 2, c4 = cg << 2;
    const int j0 = blockIdx.x * 64;
    const int r0 = blockIdx.y * 64;
    const int lr = tid >> 2, lk = (tid & 3) << 2;       // x loader
    const int wk = tid >> 4, wj = (tid & 15) << 2;      // w loader

    unsigned long long acc[4][2];
#pragma unroll
    for (int i = 0; i < 4; i++) { acc[i][0] = 0ull; acc[i][1] = 0ull; }

    for (int k0 = 0; k0 < NI; k0 += 16) {
        *(float4*)&xs[lr][lk] = *(const float4*)(x + (r0 + lr) * NI + k0 + lk);
        *(float4*)&ws[wk][wj] = *(const float4*)(g_wt + (k0 + wk) * NH + j0 + wj);
        __syncthreads();
#pragma unroll
        for (int k = 0; k < 16; k += 4) {
            ulonglong2 b0 = *(const ulonglong2*)&ws[k + 0][c4];
            ulonglong2 b1 = *(const ulonglong2*)&ws[k + 1][c4];
            ulonglong2 b2 = *(const ulonglong2*)&ws[k + 2][c4];
            ulonglong2 b3 = *(const ulonglong2*)&ws[k + 3][c4];
#pragma unroll
            for (int i = 0; i < 4; i++) {
                float4 a = *(const float4*)&xs[r4 + i][k];
                unsigned long long p;
                p = pk2(a.x, a.x); acc[i][0] = ffma2(p, b0.x, acc[i][0]); acc[i][1] = ffma2(p, b0.y, acc[i][1]);
                p = pk2(a.y, a.y); acc[i][0] = ffma2(p, b1.x, acc[i][0]); acc[i][1] = ffma2(p, b1.y, acc[i][1]);
                p = pk2(a.z, a.z); acc[i][0] = ffma2(p, b2.x, acc[i][0]); acc[i][1] = ffma2(p, b2.y, acc[i][1]);
                p = pk2(a.w, a.w); acc[i][0] = ffma2(p, b3.x, acc[i][0]); acc[i][1] = ffma2(p, b3.y, acc[i][1]);
            }
        }
        __syncthreads();
    }

    float4 bi = *(const float4*)(bias + j0 + c4);
#pragma unroll
    for (int i = 0; i < 4; i++) {
        int r = r0 + r4 + i;
        int off = r * NH + j0 + c4;
        float4 ev = *(const float4*)(eps + off);
        float2 lo = upk2(acc[i][0]);
        float2 hi = upk2(acc[i][1]);
        float4 o;
        o.x = lo.x + bi.x + NOISEF * ev.x;
        o.y = lo.y + bi.y + NOISEF * ev.y;
        o.z = hi.x + bi.z + NOISEF * ev.z;
        o.w = hi.y + bi.w + NOISEF * ev.w;
        *(float4*)(out + off) = o;
    }
}

// ---------------------------------------------------------------------------
// Persistent scan kernel: 128 blocks (nt, ks). Per step:
//   rendezvous(done >= 128*t) -> stage h slice -> GEMM -> store slab ->
//   rendezvous(cnt >= 128*(t+1)) -> distributed epilogue (8 rows/block)
// ---------------------------------------------------------------------------
__global__ void __launch_bounds__(256) scan_kernel(
    const float* __restrict__ W, float* __restrict__ out)
{
    extern __shared__ float smem[];
    float* ws_s = smem;                 // [128][64] W tile (k x j)
    float* hs_s = smem + 128 * 64;      // [64][132] h slice (b x k)
#define HS(b, k) hs_s[(b) * 132 + (k)]

    const int tid = threadIdx.x;
    const int nt = blockIdx.x & 15;
    const int ks = blockIdx.x >> 4;
    const int j0 = nt * 64;
    const int k0 = ks * 128;
    const int rg = tid >> 4, cg = tid & 15;
    const int r4 = rg << 2, c4 = cg << 2;
    // epilogue mapping: this block handles rows ks*8 .. ks*8+7 of tile nt
    const int pr = tid >> 5;            // 0..7
    const int pc = (tid & 31) << 1;     // 0..62
    const int gb = ks * 8 + pr;         // global batch row
    const int jc = j0 + pc;             // global column

    // Load W tile once: ws_s[k][j] = W[k0+k][j0+j]
    for (int idx = tid; idx < 128 * 16; idx += 256) {
        int k = idx >> 4, j = (idx & 15) << 2;
        *(float4*)&ws_s[k * 64 + j] = *(const float4*)(W + (k0 + k) * NH + j0 + j);
    }
    const float2 al = *(const float2*)(g_alpha + jc);
    __syncthreads();

    for (int t = 0; t < TT; t++) {
        // rendezvous 1: all epilogues of step t-1 complete
        if (t > 0) {
            if (tid == 0) { while (__ldcg(&g_done) < NBLK * t) __nanosleep(64); }
            __syncthreads();
        }

        // stage h slice: hs_s[b][k] = h_in[b][k0+k]
        const float* hin = g_h[t & 1];
        {
            int b = tid >> 5, kk = (tid & 31) << 2;
#pragma unroll
            for (int it = 0; it < 8; it++) {
                float4 v = __ldcg((const float4*)(hin + (b + it * 8) * NH + k0 + kk));
                *(float4*)&HS(b + it * 8, kk) = v;
            }
        }
        __syncthreads();

        // partial GEMM: 4 rows x 4 cols per thread over K=128, FFMA2
        unsigned long long acc[4][2];
#pragma unroll
        for (int i = 0; i < 4; i++) { acc[i][0] = 0ull; acc[i][1] = 0ull; }
#pragma unroll 4
        for (int k = 0; k < 128; k += 4) {
            ulonglong2 b0 = *(const ulonglong2*)&ws_s[(k + 0) * 64 + c4];
            ulonglong2 b1 = *(const ulonglong2*)&ws_s[(k + 1) * 64 + c4];
            ulonglong2 b2 = *(const ulonglong2*)&ws_s[(k + 2) * 64 + c4];
            ulonglong2 b3 = *(const ulonglong2*)&ws_s[(k + 3) * 64 + c4];
#pragma unroll
            for (int i = 0; i < 4; i++) {
                float4 a = *(const float4*)&HS(r4 + i, k);
                unsigned long long p;
                p = pk2(a.x, a.x); acc[i][0] = ffma2(p, b0.x, acc[i][0]); acc[i][1] = ffma2(p, b0.y, acc[i][1]);
                p = pk2(a.y, a.y); acc[i][0] = ffma2(p, b1.x, acc[i][0]); acc[i][1] = ffma2(p, b1.y, acc[i][1]);
                p = pk2(a.z, a.z); acc[i][0] = ffma2(p, b2.x, acc[i][0]); acc[i][1] = ffma2(p, b2.y, acc[i][1]);
                p = pk2(a.w, a.w); acc[i][0] = ffma2(p, b3.x, acc[i][0]); acc[i][1] = ffma2(p, b3.y, acc[i][1]);
            }
        }

        // store partial slab (unique region per (ks,nt): plain stores, row-major)
        {
            float* part = g_part[ks];
#pragma unroll
            for (int i = 0; i < 4; i++) {
                float2 lo = upk2(acc[i][0]);
                float2 hi = upk2(acc[i][1]);
                *(float4*)(part + (r4 + i) * NH + j0 + c4) = make_float4(lo.x, lo.y, hi.x, hi.y);
            }
        }

        // prefetch epilogue operands (independent of slabs) to hide latency
        const long ooff = ((long)gb * TT + t) * NH + jc;
        float2 pre = *(const float2*)(out + ooff);
        float2 hv  = __ldcg((const float2*)(hin + gb * NH + jc));

        __threadfence();
        __syncthreads();
        if (tid == 0) {
            atomicAdd(&g_cnt, 1);
            // rendezvous 2: all 128 slabs of step t present
            while (__ldcg(&g_cnt) < NBLK * (t + 1)) __nanosleep(64);
        }
        __syncthreads();

        // distributed epilogue: sum 8 slabs (fixed order) for rows gb, cols jc..jc+1
        {
            float2 s = __ldcg((const float2*)(g_part[0] + gb * NH + jc));
#pragma unroll
            for (int q = 1; q < KS; q++) {
                float2 v = __ldcg((const float2*)(g_part[q] + gb * NH + jc));
                s.x += v.x; s.y += v.y;
            }
            float2 hn;
            hn.x = (1.0f - al.x) * hv.x + al.x * tanhf(pre.x + s.x);
            hn.y = (1.0f - al.y) * hv.y + al.y * tanhf(pre.y + s.y);
            *(float2*)(out + ooff) = hn;
            *(float2*)(g_h[(t + 1) & 1] + gb * NH + jc) = hn;
        }

        __threadfence();
        __syncthreads();
        if (tid == 0) atomicAdd(&g_done, 1);
    }
#undef HS
}

extern "C" void kernel_launch(void* const* d_in, const int* in_sizes, int n_in,
                              void* d_out, int out_size) {
    const float* x    = (const float*)d_in[0];  // [B,T,I]
    const float* eps  = (const float*)d_in[1];  // [B,T,H]
    const float* in_w = (const float*)d_in[2];  // [H,I]
    const float* in_b = (const float*)d_in[3];  // [H]
    const float* W    = (const float*)d_in[4];  // [H,H]
    const float* taus = (const float*)d_in[5];  // [H]
    float* out = (float*)d_out;                 // [B,T,H]

    static int attr_done = 0;
    const int scan_smem = (128 * 64 + 64 * 132) * sizeof(float);  // ~66.6 KB
    if (!attr_done) {
        cudaFuncSetAttribute(scan_kernel, cudaFuncAttributeMaxDynamicSharedMemorySize, scan_smem);
        attr_done = 1;
    }

    init_kernel<<<(NB * NH + 255) / 256, 256>>>(taus);
    transpose_kernel<<<dim3(NI / 32, NH / 32), dim3(32, 8)>>>(in_w);

    dim3 pgrid(NH / 64, (NB * TT) / 64);   // (16, 512)
    proj_kernel<<<pgrid, 256>>>(x, in_b, eps, out);

    scan_kernel<<<NBLK, 256, scan_smem>>>(W, out);
}